// round 10
// baseline (speedup 1.0000x reference)
#include <cuda_runtime.h>
#include <math.h>

#define KS 11
#define CH 32     // output rows per chunk
#define HRX 42    // resident rows / strip width + halo
#define SP 44     // padded float2 row stride
#define RY 4

typedef unsigned long long ull;

__device__ __forceinline__ ull pk2(float lo, float hi) {
    ull r; asm("mov.b64 %0,{%1,%2};" : "=l"(r) : "f"(lo), "f"(hi)); return r;
}
__device__ __forceinline__ void upk2(ull v, float& lo, float& hi) {
    asm("mov.b64 {%0,%1},%2;" : "=f"(lo), "=f"(hi) : "l"(v));
}
__device__ __forceinline__ ull fma2(ull a, ull b, ull c) {
    ull d; asm("fma.rn.f32x2 %0,%1,%2,%3;" : "=l"(d) : "l"(a), "l"(b), "l"(c)); return d;
}
__device__ __forceinline__ ull mul2(ull a, ull b) {
    ull d; asm("mul.rn.f32x2 %0,%1,%2;" : "=l"(d) : "l"(a), "l"(b)); return d;
}
__device__ __forceinline__ ull add2(ull a, ull b) {
    ull d; asm("add.rn.f32x2 %0,%1,%2;" : "=l"(d) : "l"(a), "l"(b)); return d;
}
__device__ __forceinline__ float frcp(float x) {
    float r; asm("rcp.approx.f32 %0, %1;" : "=f"(r) : "f"(x)); return r;
}

__device__ constexpr float GW[KS] = {
    0.00102836f, 0.00759866f, 0.03600077f, 0.10936069f, 0.21300566f,
    0.26601190f,
    0.21300566f, 0.10936069f, 0.03600077f, 0.00759866f, 0.00102836f
};
__device__ __forceinline__ ull WPK(const ull* w, int k) {
    return w[k < 6 ? k : 10 - k];
}

__device__ float2 g_P0[3538944];
__device__ float2 g_P1[884736];
__device__ float g_acc[5 * 96 * 2];

__global__ void zero_acc_kernel() {
    int i = threadIdx.x;
    if (i < 5 * 96 * 2) g_acc[i] = 0.f;
}

// Streaming column-band SSIM: block = 32-wide strip, marches down in 32-row
// chunks keeping a 42-row h-blurred window resident. (s,d,ss,dd) 4-stream f32x2.
__global__ __launch_bounds__(256, 5)
void ssim_kernel(const float* __restrict__ X, const float* __restrict__ Y,
                 const float2* __restrict__ SDin, float2* __restrict__ SDout,
                 int W, int OW, int scale)
{
    __shared__ float2 sIN[HRX][SP];
    __shared__ float4 sH[HRX][32];
    __shared__ float rs[8], rc[8];

    const int tx = threadIdx.x, ty = threadIdx.y;
    const int t = ty * 32 + tx;
    const int x0 = blockIdx.x * 32;
    const int bc = blockIdx.y;
    const int W2 = W >> 1;
    const int nc = (OW + CH - 1) / CH;
    const bool xin = (x0 + HRX <= W);

    const float2* Sb = SDin ? SDin + (size_t)bc * W * W : nullptr;
    const float*  Xb = X ? X + (size_t)bc * W * W : nullptr;
    const float*  Yb = Y ? Y + (size_t)bc * W * W : nullptr;

    ull wpk[6];
    #pragma unroll
    for (int k = 0; k < 6; k++) wpk[k] = pk2(GW[k], GW[k]);

    float ssum = 0.f, csum = 0.f;

    // Load n global rows starting at g0 into sIN rows r0.. (cols x0..x0+41, zero-pad OOB)
    auto load_rows = [&](int g0, int r0, int n) {
        int total = n * 21;
        for (int i = t; i < total; i += 256) {
            int rr = i / 21, cp = (i - rr * 21) * 2;
            int gy = g0 + rr;
            float4 v = make_float4(0.f, 0.f, 0.f, 0.f);
            if (SDin) {
                if (xin && gy < W) {
                    v = *(const float4*)&Sb[(size_t)gy * W + x0 + cp];
                } else if (gy < W) {
                    int c0 = x0 + cp;
                    if (c0 < W)     { float2 a = Sb[(size_t)gy * W + c0];     v.x = a.x; v.y = a.y; }
                    if (c0 + 1 < W) { float2 b = Sb[(size_t)gy * W + c0 + 1]; v.z = b.x; v.w = b.y; }
                }
            } else {
                if (xin && gy < W) {
                    size_t o = (size_t)gy * W + x0 + cp;
                    float2 xv = *(const float2*)(Xb + o);
                    float2 yv = *(const float2*)(Yb + o);
                    v = make_float4(xv.x + yv.x, xv.x - yv.x, xv.y + yv.y, xv.y - yv.y);
                } else if (gy < W) {
                    int c0 = x0 + cp;
                    if (c0 < W)     { float a = Xb[(size_t)gy * W + c0],     b = Yb[(size_t)gy * W + c0];     v.x = a + b; v.y = a - b; }
                    if (c0 + 1 < W) { float a = Xb[(size_t)gy * W + c0 + 1], b = Yb[(size_t)gy * W + c0 + 1]; v.z = a + b; v.w = a - b; }
                }
            }
            *(float4*)&sIN[r0 + rr][cp] = v;
        }
    };

    // Horizontal blur of sIN rows r0..r0+n-1 into sH (warp = row)
    auto hpass = [&](int r0, int n) {
        for (int r = r0 + ty; r < r0 + n; r += 8) {
            ull a01e = 0ULL, a01o = 0ULL, a23e = 0ULL, a23o = 0ULL;
            #pragma unroll
            for (int k = 0; k < KS; k += 2) {
                float2 v = sIN[r][tx + k];
                ull pv = pk2(v.x, v.y);
                a01e = fma2(pv, WPK(wpk, k), a01e);
                a23e = fma2(mul2(pv, pv), WPK(wpk, k), a23e);
            }
            #pragma unroll
            for (int k = 1; k < KS; k += 2) {
                float2 v = sIN[r][tx + k];
                ull pv = pk2(v.x, v.y);
                a01o = fma2(pv, WPK(wpk, k), a01o);
                a23o = fma2(mul2(pv, pv), WPK(wpk, k), a23o);
            }
            ull a01 = add2(a01e, a01o), a23 = add2(a23e, a23o);
            float b0, b1, b2, b3;
            upk2(a01, b0, b1); upk2(a23, b2, b3);
            sH[r][tx] = make_float4(b0, b1, b2, b3);
        }
    };

    // Fused 2x2 pool: sIN rows 0..31 (= global rows 32c..32c+31) -> pool rows 16c..
    auto pool = [&](int c) {
        if (!SDout) return;
        int px = t & 15, py = t >> 4;
        int gx2 = (x0 >> 1) + px, gy2 = 16 * c + py;
        if (gx2 < W2 && gy2 < W2) {
            float2 a = sIN[2 * py][2 * px],     b = sIN[2 * py][2 * px + 1];
            float2 cc = sIN[2 * py + 1][2 * px], d = sIN[2 * py + 1][2 * px + 1];
            float2 o;
            o.x = 0.25f * (a.x + b.x + cc.x + d.x);
            o.y = 0.25f * (a.y + b.y + cc.y + d.y);
            SDout[(size_t)bc * W2 * W2 + (size_t)gy2 * W2 + gx2] = o;
        }
    };

    // Vertical blur + SSIM for chunk c (outputs rows 32c..32c+31)
    auto vpass = [&](int c) {
        ull amu[RY], asg[RY];
        #pragma unroll
        for (int j = 0; j < RY; j++) { amu[j] = 0ULL; asg[j] = 0ULL; }
        const int rbase = ty * RY;
        #pragma unroll
        for (int rr = 0; rr < RY - 1 + KS; rr++) {
            float4 u = sH[rbase + rr][tx];
            ull p01 = pk2(u.x, u.y), p23 = pk2(u.z, u.w);
            #pragma unroll
            for (int j = 0; j < RY; j++) {
                int k = rr - j;
                if (k >= 0 && k < KS) {
                    amu[j] = fma2(p01, WPK(wpk, k), amu[j]);
                    asg[j] = fma2(p23, WPK(wpk, k), asg[j]);
                }
            }
        }
        const int ox = x0 + tx;
        #pragma unroll
        for (int j = 0; j < RY; j++) {
            int oy = CH * c + rbase + j;
            if (ox < OW && oy < OW) {
                float ms2, md2, bss, bdd;
                upk2(mul2(amu[j], amu[j]), ms2, md2);
                upk2(asg[j], bss, bdd);
                const float C1 = 6.5025f, C2 = 58.5225f;
                float musum = 0.5f * (ms2 + md2);
                float mu2x  = 0.5f * (ms2 - md2);
                float sqsum = 0.5f * (bss + bdd);
                float xy2   = 0.5f * (bss - bdd);
                float A  = (xy2 - mu2x) + C2;
                float B  = (sqsum - musum) + C2;
                float Cn = mu2x + C1;
                float D  = musum + C1;
                float inv = frcp(B * D);
                csum += A * D * inv;
                ssum += A * Cn * inv;
            }
        }
    };

    // ---- prologue ----
    load_rows(0, 0, HRX);
    __syncthreads();
    hpass(0, HRX);
    pool(0);
    __syncthreads();
    vpass(0);

    // ---- streaming chunks ----
    for (int c = 1; c < nc; c++) {
        // register-stage the 10 overlap rows (reads race-free with vpass reads)
        float4 hs0, hs1; float2 is0, is1;
        int i1 = t + 256;
        if (t < 320)  hs0 = sH[32 + (t >> 5)][t & 31];
        if (i1 < 320) hs1 = sH[32 + (i1 >> 5)][i1 & 31];
        if (t < 420)  is0 = sIN[32 + t / 42][t % 42];
        if (i1 < 420) is1 = sIN[32 + i1 / 42][i1 % 42];
        __syncthreads();
        if (t < 320)  sH[t >> 5][t & 31] = hs0;
        if (i1 < 320) sH[i1 >> 5][i1 & 31] = hs1;
        if (t < 420)  sIN[t / 42][t % 42] = is0;
        if (i1 < 420) sIN[i1 / 42][i1 % 42] = is1;
        load_rows(CH * c + 10, 10, 32);
        __syncthreads();
        hpass(10, 32);
        pool(c);
        __syncthreads();
        vpass(c);
    }

    // ---- reduce ----
    #pragma unroll
    for (int off = 16; off; off >>= 1) {
        ssum += __shfl_down_sync(0xffffffffu, ssum, off);
        csum += __shfl_down_sync(0xffffffffu, csum, off);
    }
    if (tx == 0) { rs[ty] = ssum; rc[ty] = csum; }
    __syncthreads();
    if (t == 0) {
        float a = 0.f, b = 0.f;
        #pragma unroll
        for (int i = 0; i < 8; i++) { a += rs[i]; b += rc[i]; }
        atomicAdd(&g_acc[(scale * 96 + bc) * 2 + 0], a);
        atomicAdd(&g_acc[(scale * 96 + bc) * 2 + 1], b);
    }
}

__global__ void finalize_kernel(float* __restrict__ out) {
    __shared__ float sh[96];
    const int i = threadIdx.x;
    const float wts[5]  = {0.0448f, 0.2856f, 0.3001f, 0.2363f, 0.1333f};
    const float cnts[5] = {374.f * 374.f, 182.f * 182.f, 86.f * 86.f, 38.f * 38.f, 14.f * 14.f};
    if (i < 96) {
        float p = 1.f;
        #pragma unroll
        for (int s = 0; s < 5; s++) {
            int comp = (s < 4) ? 1 : 0;
            float m = g_acc[(s * 96 + i) * 2 + comp] / cnts[s];
            m = fmaxf(m, 0.f);
            p *= powf(m, wts[s]);
        }
        sh[i] = p;
    }
    __syncthreads();
    if (i == 0) {
        float s = 0.f;
        for (int j = 0; j < 96; j++) s += sh[j];
        out[0] = 1.f - s / 96.f;
    }
}

extern "C" void kernel_launch(void* const* d_in, const int* in_sizes, int n_in,
                              void* d_out, int out_size)
{
    const float* X = (const float*)d_in[0];
    const float* Y = (const float*)d_in[1];
    float* out = (float*)d_out;

    float2 *P0, *P1;
    cudaGetSymbolAddress((void**)&P0, g_P0);
    cudaGetSymbolAddress((void**)&P1, g_P1);

    zero_acc_kernel<<<1, 960>>>();

    dim3 blk(32, 8);
    auto mkgrid = [](int OW) {
        return dim3((OW + 31) / 32, 96);
    };

    // scale 0: reads X,Y; pools 192^2 (s,d) into P0
    ssim_kernel<<<mkgrid(374), blk>>>(X, Y, nullptr, P0, 384, 374, 0);
    // scale 1: reads P0; pools 96^2 into P1
    ssim_kernel<<<mkgrid(182), blk>>>(nullptr, nullptr, P0, P1, 192, 182, 1);
    // scale 2: reads P1; pools 48^2 into P0
    ssim_kernel<<<mkgrid(86), blk>>>(nullptr, nullptr, P1, P0, 96, 86, 2);
    // scale 3: reads P0; pools 24^2 into P1
    ssim_kernel<<<mkgrid(38), blk>>>(nullptr, nullptr, P0, P1, 48, 38, 3);
    // scale 4: reads P1; no pool
    ssim_kernel<<<mkgrid(14), blk>>>(nullptr, nullptr, P1, nullptr, 24, 14, 4);

    finalize_kernel<<<1, 96>>>(out);
}

// round 11
// speedup vs baseline: 1.1988x; 1.1988x over previous
#include <cuda_runtime.h>
#include <math.h>

#define KS 11
#define TILE 32
#define TYB 8
#define RY 4
#define HR 42   // TILE + 10
#define SP 44   // padded float2 row stride (16B-aligned rows)

typedef unsigned long long ull;

__device__ __forceinline__ ull pk2(float lo, float hi) {
    ull r; asm("mov.b64 %0,{%1,%2};" : "=l"(r) : "f"(lo), "f"(hi)); return r;
}
__device__ __forceinline__ void upk2(ull v, float& lo, float& hi) {
    asm("mov.b64 {%0,%1},%2;" : "=f"(lo), "=f"(hi) : "l"(v));
}
__device__ __forceinline__ ull fma2(ull a, ull b, ull c) {
    ull d; asm("fma.rn.f32x2 %0,%1,%2,%3;" : "=l"(d) : "l"(a), "l"(b), "l"(c)); return d;
}
__device__ __forceinline__ ull mul2(ull a, ull b) {
    ull d; asm("mul.rn.f32x2 %0,%1,%2;" : "=l"(d) : "l"(a), "l"(b)); return d;
}
__device__ __forceinline__ float frcp(float x) {
    float r; asm("rcp.approx.f32 %0, %1;" : "=f"(r) : "f"(x)); return r;
}

__device__ constexpr float GW[KS] = {
    0.00102836f, 0.00759866f, 0.03600077f, 0.10936069f, 0.21300566f,
    0.26601190f,
    0.21300566f, 0.10936069f, 0.03600077f, 0.00759866f, 0.00102836f
};
// symmetric weight lookup (k may be 0..10; only 6 unique regs)
__device__ __forceinline__ ull WPK(const ull* w, int k) {
    return w[k < 6 ? k : 10 - k];
}

// Pyramid scratch in (s,d) float2 form
__device__ float2 g_P0[3538944];
__device__ float2 g_P1[884736];
__device__ float g_acc[5 * 96 * 2];

__global__ void zero_acc_kernel() {
    int i = threadIdx.x;
    if (i < 5 * 96 * 2) g_acc[i] = 0.f;
}

// 4-stream SSIM (s=x+y, d=x-y, ss, dd), packed f32x2, 32x32 tile, RY=4.
// h-pass: warp = 2 rows x 16 lane-pairs, aligned LDS.128 reads, RX=2 outputs/lane,
// column-permuted sH stores (phys col j & 16+j hold logical cols 2j & 2j+1).
__global__ __launch_bounds__(256)
void ssim_kernel(const float* __restrict__ X, const float* __restrict__ Y,
                 const float2* __restrict__ SDin, float2* __restrict__ SDout,
                 int W, int OW, int scale)
{
    __shared__ float2 sSD[HR][SP];
    __shared__ float4 sH[HR][TILE];
    __shared__ float rs[TYB], rc[TYB];

    const int tx = threadIdx.x, ty = threadIdx.y;
    const int t = ty * 32 + tx;
    const int x0 = blockIdx.x * TILE, y0 = blockIdx.y * TILE;
    const int bc = blockIdx.z;
    const bool interior = (x0 + HR <= W) && (y0 + HR <= W);

    // ---- Load input tile with halo ----
    if (SDin) {
        const float2* Sb = SDin + (size_t)bc * W * W;
        if (interior) {
            for (int i = t; i < HR * 21; i += 256) {
                int r = i / 21, cp = (i - r * 21) * 2;
                float4 v = *(const float4*)&Sb[(size_t)(y0 + r) * W + x0 + cp];
                *(float4*)&sSD[r][cp] = v;
            }
        } else {
            for (int idx = t; idx < HR * HR; idx += 256) {
                int r = idx / HR, c = idx - r * HR;
                int gx = x0 + c, gy = y0 + r;
                float2 v = make_float2(0.f, 0.f);
                if (gx < W && gy < W) v = Sb[(size_t)gy * W + gx];
                sSD[r][c] = v;
            }
        }
    } else {
        const float* Xb = X + (size_t)bc * W * W;
        const float* Yb = Y + (size_t)bc * W * W;
        if (interior) {
            for (int i = t; i < HR * 21; i += 256) {
                int r = i / 21, cp = (i - r * 21) * 2;
                size_t o = (size_t)(y0 + r) * W + x0 + cp;
                float2 xv = *(const float2*)(Xb + o);
                float2 yv = *(const float2*)(Yb + o);
                float4 v = make_float4(xv.x + yv.x, xv.x - yv.x,
                                       xv.y + yv.y, xv.y - yv.y);
                *(float4*)&sSD[r][cp] = v;
            }
        } else {
            for (int idx = t; idx < HR * HR; idx += 256) {
                int r = idx / HR, c = idx - r * HR;
                int gx = x0 + c, gy = y0 + r;
                float xv = 0.f, yv = 0.f;
                if (gx < W && gy < W) {
                    size_t o = (size_t)gy * W + gx;
                    xv = Xb[o]; yv = Yb[o];
                }
                sSD[r][c] = make_float2(xv + yv, xv - yv);
            }
        }
    }
    __syncthreads();

    // ---- Fused 2x2 pool into next-scale (s,d) buffer ----
    if (SDout) {
        int W2 = W >> 1;
        int cx = t & 15, cy = t >> 4;
        int gx2 = (x0 >> 1) + cx, gy2 = (y0 >> 1) + cy;
        if (gx2 < W2 && gy2 < W2) {
            float2 a = sSD[2 * cy][2 * cx],     b = sSD[2 * cy][2 * cx + 1];
            float2 c = sSD[2 * cy + 1][2 * cx], d = sSD[2 * cy + 1][2 * cx + 1];
            float2 o;
            o.x = 0.25f * (a.x + b.x + c.x + d.x);
            o.y = 0.25f * (a.y + b.y + c.y + d.y);
            SDout[(size_t)bc * W2 * W2 + (size_t)gy2 * W2 + gx2] = o;
        }
    }

    ull wpk[6];
    #pragma unroll
    for (int k = 0; k < 6; k++) wpk[k] = pk2(GW[k], GW[k]);

    // ---- Horizontal blur: warp = 2 rows, lane = (half, col-pair j), RX=2 ----
    {
        const int half = tx >> 4;
        const int j = tx & 15;
        #pragma unroll
        for (int rp = 0; rp < HR / 2; rp += TYB) {
            int p = rp + ty;
            if (p < HR / 2) {
                const int r = 2 * p + half;
                ull s0 = 0ULL, q0 = 0ULL, s1 = 0ULL, q1 = 0ULL;
                #pragma unroll
                for (int m = 0; m < 6; m++) {
                    float4 v = *(const float4*)&sSD[r][2 * j + 2 * m];
                    ull pa = pk2(v.x, v.y), pb = pk2(v.z, v.w);
                    ull qa = mul2(pa, pa),  qb = mul2(pb, pb);
                    s0 = fma2(pa, WPK(wpk, 2 * m), s0);
                    q0 = fma2(qa, WPK(wpk, 2 * m), q0);
                    s1 = fma2(pb, WPK(wpk, 2 * m), s1);
                    q1 = fma2(qb, WPK(wpk, 2 * m), q1);
                    if (m < 5) {
                        s0 = fma2(pb, WPK(wpk, 2 * m + 1), s0);
                        q0 = fma2(qb, WPK(wpk, 2 * m + 1), q0);
                    }
                    if (m > 0) {
                        s1 = fma2(pa, WPK(wpk, 2 * m - 1), s1);
                        q1 = fma2(qa, WPK(wpk, 2 * m - 1), q1);
                    }
                }
                float b0, b1, b2, b3;
                // logical col 2j -> phys col j ; logical col 2j+1 -> phys col 16+j
                upk2(s0, b0, b1); upk2(q0, b2, b3);
                sH[r][j] = make_float4(b0, b1, b2, b3);
                upk2(s1, b0, b1); upk2(q1, b2, b3);
                sH[r][16 + j] = make_float4(b0, b1, b2, b3);
            }
        }
    }
    __syncthreads();

    // ---- Vertical blur + SSIM, RY=4 outputs per thread (permuted columns) ----
    ull amu[RY], asg[RY];
    #pragma unroll
    for (int jj = 0; jj < RY; jj++) { amu[jj] = 0ULL; asg[jj] = 0ULL; }
    const int rbase = ty * RY;
    #pragma unroll
    for (int rr = 0; rr < RY - 1 + KS; rr++) {
        float4 u = sH[rbase + rr][tx];
        ull p01 = pk2(u.x, u.y), p23 = pk2(u.z, u.w);
        #pragma unroll
        for (int jj = 0; jj < RY; jj++) {
            int k = rr - jj;
            if (k >= 0 && k < KS) {
                amu[jj] = fma2(p01, WPK(wpk, k), amu[jj]);
                asg[jj] = fma2(p23, WPK(wpk, k), asg[jj]);
            }
        }
    }

    float ssum = 0.f, csum = 0.f;
    const int lc = (tx < 16) ? (2 * tx) : (2 * (tx - 16) + 1);  // logical column
    const int ox = x0 + lc;
    #pragma unroll
    for (int jj = 0; jj < RY; jj++) {
        int oy = y0 + rbase + jj;
        if (ox < OW && oy < OW) {
            float ms2, md2, bss, bdd;
            upk2(mul2(amu[jj], amu[jj]), ms2, md2);
            upk2(asg[jj], bss, bdd);
            const float C1 = 6.5025f, C2 = 58.5225f;
            float musum  = 0.5f * (ms2 + md2);
            float mu2x   = 0.5f * (ms2 - md2);
            float sqsum  = 0.5f * (bss + bdd);
            float xy2    = 0.5f * (bss - bdd);
            float A  = (xy2 - mu2x) + C2;
            float B  = (sqsum - musum) + C2;
            float Cn = mu2x + C1;
            float D  = musum + C1;
            float inv = frcp(B * D);
            csum += A * D * inv;
            ssum += A * Cn * inv;
        }
    }

    #pragma unroll
    for (int off = 16; off; off >>= 1) {
        ssum += __shfl_down_sync(0xffffffffu, ssum, off);
        csum += __shfl_down_sync(0xffffffffu, csum, off);
    }
    if (tx == 0) { rs[ty] = ssum; rc[ty] = csum; }
    __syncthreads();
    if (t == 0) {
        float a = 0.f, b = 0.f;
        #pragma unroll
        for (int i = 0; i < TYB; i++) { a += rs[i]; b += rc[i]; }
        atomicAdd(&g_acc[(scale * 96 + bc) * 2 + 0], a);
        atomicAdd(&g_acc[(scale * 96 + bc) * 2 + 1], b);
    }
}

__global__ void finalize_kernel(float* __restrict__ out) {
    __shared__ float sh[96];
    const int i = threadIdx.x;
    const float wts[5]  = {0.0448f, 0.2856f, 0.3001f, 0.2363f, 0.1333f};
    const float cnts[5] = {374.f * 374.f, 182.f * 182.f, 86.f * 86.f, 38.f * 38.f, 14.f * 14.f};
    if (i < 96) {
        float p = 1.f;
        #pragma unroll
        for (int s = 0; s < 5; s++) {
            int comp = (s < 4) ? 1 : 0;
            float m = g_acc[(s * 96 + i) * 2 + comp] / cnts[s];
            m = fmaxf(m, 0.f);
            p *= powf(m, wts[s]);
        }
        sh[i] = p;
    }
    __syncthreads();
    if (i == 0) {
        float s = 0.f;
        for (int j = 0; j < 96; j++) s += sh[j];
        out[0] = 1.f - s / 96.f;
    }
}

extern "C" void kernel_launch(void* const* d_in, const int* in_sizes, int n_in,
                              void* d_out, int out_size)
{
    const float* X = (const float*)d_in[0];
    const float* Y = (const float*)d_in[1];
    float* out = (float*)d_out;

    float2 *P0, *P1;
    cudaGetSymbolAddress((void**)&P0, g_P0);
    cudaGetSymbolAddress((void**)&P1, g_P1);

    zero_acc_kernel<<<1, 960>>>();

    dim3 blk(32, TYB);
    auto mkgrid = [](int OW) {
        int g = (OW + TILE - 1) / TILE;
        return dim3(g, g, 96);
    };

    // scale 0: reads X,Y; pools 192^2 (s,d) into P0
    ssim_kernel<<<mkgrid(374), blk>>>(X, Y, nullptr, P0, 384, 374, 0);
    // scale 1: reads P0; pools 96^2 into P1
    ssim_kernel<<<mkgrid(182), blk>>>(nullptr, nullptr, P0, P1, 192, 182, 1);
    // scale 2: reads P1; pools 48^2 into P0
    ssim_kernel<<<mkgrid(86), blk>>>(nullptr, nullptr, P1, P0, 96, 86, 2);
    // scale 3: reads P0; pools 24^2 into P1
    ssim_kernel<<<mkgrid(38), blk>>>(nullptr, nullptr, P0, P1, 48, 38, 3);
    // scale 4: reads P1; no pool
    ssim_kernel<<<mkgrid(14), blk>>>(nullptr, nullptr, P1, nullptr, 24, 14, 4);

    finalize_kernel<<<1, 96>>>(out);
}